// round 13
// baseline (speedup 1.0000x reference)
#include <cuda_runtime.h>
#include <cuda_fp16.h>
#include <cstdint>

#define DD 128
#define MAX_R 8
#define MAX_N 50000
#define NG 9                    // 8 relations + self (W0)
#define RN (MAX_R * MAX_N)      // 400000 segments
#define MAX_E 1000000

// ---------------- device scratch (no allocs allowed) ----------------
__device__ __half g_agg[(size_t)RN * DD];               // per-(rel,dst) scaled sums, 102.4 MB
__device__ __half g_x16[(size_t)MAX_N * DD];            // fp16 X, 12.8 MB (L2-resident)
__device__ __half g_wh [(size_t)NG * DD * DD];          // fp16 W^T, [g][n][k]
__device__ int    g_cnt[RN];                            // counts -> cursors -> ends
__device__ int    g_start[RN];                          // segment range starts
__device__ int    g_cursor;                             // global range allocator
__device__ int    g_srcs[MAX_E];                        // segment-sorted src indices

__device__ __forceinline__ uint32_t smem_u32(const void* p) {
    uint32_t a;
    asm("{ .reg .u64 t; cvta.to.shared.u64 t, %1; cvt.u32.u64 %0, t; }" : "=r"(a) : "l"(p));
    return a;
}

// ---------------- prep: zero seg counters + fp16(X) + fp16(W^T) ----------------
#define CZ (RN / 4)                                     // 100,000 uint4 counter zeros
#define XC (MAX_N * DD / 8)                             // 800,000 x-convert items
#define WC (NG * DD * DD)                               // 147,456 w-convert scalars
__global__ void prep_kernel(const float* __restrict__ X,
                            const float* __restrict__ W,
                            const float* __restrict__ W0)
{
    int i = blockIdx.x * blockDim.x + threadIdx.x;
    if (i < CZ) {
        ((uint4*)g_cnt)[i] = make_uint4(0, 0, 0, 0);
    } else if (i < CZ + XC) {
        int j = i - CZ;                                  // 8 floats -> 8 halves
        float4 f0 = ((const float4*)X)[j * 2];
        float4 f1 = ((const float4*)X)[j * 2 + 1];
        uint4 o;
        *(__half2*)&o.x = __floats2half2_rn(f0.x, f0.y);
        *(__half2*)&o.y = __floats2half2_rn(f0.z, f0.w);
        *(__half2*)&o.z = __floats2half2_rn(f1.x, f1.y);
        *(__half2*)&o.w = __floats2half2_rn(f1.z, f1.w);
        ((uint4*)g_x16)[j] = o;
    } else if (i < CZ + XC + WC) {
        int j = i - CZ - XC;
        int g = j / (DD * DD);
        int rem = j - g * DD * DD;
        int n = rem >> 7, k = rem & 127;                 // dest layout [g][n][k]
        float w = (g < MAX_R) ? W[(size_t)g * DD * DD + (size_t)k * DD + n]
                              : W0[(size_t)k * DD + n];
        g_wh[j] = __float2half_rn(w);
    } else if (i == CZ + XC + WC) {
        g_cursor = 0;
    }
}

// ---------------- CSR pass A: per-segment edge counts ----------------
__global__ void count_kernel(const int* __restrict__ edst,
                             const int* __restrict__ erel, int E, int N)
{
    int e = blockIdx.x * blockDim.x + threadIdx.x;
    if (e >= E) return;
    atomicAdd(&g_cnt[erel[e] * N + edst[e]], 1);
}

// ---------------- CSR pass B: disjoint range allocation (block-scan + 1 atomic) ----
__global__ __launch_bounds__(1024)
void offsets_kernel()
{
    __shared__ int wsum[32], wbase[32], bbase;
    int t = threadIdx.x, lane = t & 31, wid = t >> 5;
    int i = blockIdx.x * 1024 + t;
    int c = (i < RN) ? g_cnt[i] : 0;
    int incl = c;
    #pragma unroll
    for (int o = 1; o < 32; o <<= 1) {
        int nv = __shfl_up_sync(0xffffffffu, incl, o);
        if (lane >= o) incl += nv;
    }
    if (lane == 31) wsum[wid] = incl;
    __syncthreads();
    if (wid == 0) {
        int v = wsum[lane];
        int wi = v;
        #pragma unroll
        for (int o = 1; o < 32; o <<= 1) {
            int nv = __shfl_up_sync(0xffffffffu, wi, o);
            if (lane >= o) wi += nv;
        }
        wbase[lane] = wi - v;                            // exclusive warp base
        if (lane == 31) bbase = atomicAdd(&g_cursor, wi); // wi == block total
    }
    __syncthreads();
    if (i < RN) {
        int st = bbase + wbase[wid] + (incl - c);
        g_start[i] = st;
        g_cnt[i] = st;                                   // reuse as running cursor
    }
}

// ---------------- CSR pass C: reorder src indices into segment ranges ----------
__global__ void reorder_kernel(const int* __restrict__ esrc,
                               const int* __restrict__ edst,
                               const int* __restrict__ erel, int E, int N)
{
    int e = blockIdx.x * blockDim.x + threadIdx.x;
    if (e >= E) return;
    int seg = erel[e] * N + edst[e];
    int pos = atomicAdd(&g_cnt[seg], 1);                 // after: g_cnt[seg] == end
    g_srcs[pos] = esrc[e];
}

// ---------------- gather: agg[seg] = inv_norm[seg] * sum_{e in seg} x16[src_e] ----
// Half-warp per segment: 16 lanes x 16B = 256B row; fp32 accumulation, plain STG.
__global__ void gather_kernel(const float* __restrict__ inv_norm)
{
    int warp = blockIdx.x * (blockDim.x >> 5) + (threadIdx.x >> 5);
    int lane = threadIdx.x & 31;
    int seg = warp * 2 + (lane >> 4);
    if (seg >= RN) return;
    int half = lane & 15;

    int s0 = __ldg(&g_start[seg]);
    int s1 = __ldg(&g_cnt[seg]);

    float a0 = 0.f, a1 = 0.f, a2 = 0.f, a3 = 0.f,
          a4 = 0.f, a5 = 0.f, a6 = 0.f, a7 = 0.f;
    for (int e = s0; e < s1; ++e) {
        int src = __ldg(&g_srcs[e]);
        uint4 v = __ldg((const uint4*)(g_x16 + (size_t)src * DD) + half);
        float2 f;
        f = __half22float2(*(__half2*)&v.x); a0 += f.x; a1 += f.y;
        f = __half22float2(*(__half2*)&v.y); a2 += f.x; a3 += f.y;
        f = __half22float2(*(__half2*)&v.z); a4 += f.x; a5 += f.y;
        f = __half22float2(*(__half2*)&v.w); a6 += f.x; a7 += f.y;
    }
    float sc = __ldg(&inv_norm[seg]);                    // inv_norm layout == seg layout
    uint4 o;
    *(__half2*)&o.x = __floats2half2_rn(a0 * sc, a1 * sc);
    *(__half2*)&o.y = __floats2half2_rn(a2 * sc, a3 * sc);
    *(__half2*)&o.z = __floats2half2_rn(a4 * sc, a5 * sc);
    *(__half2*)&o.w = __floats2half2_rn(a6 * sc, a7 * sc);
    ((uint4*)(g_agg + (size_t)seg * DD))[half] = o;
}

// ---------------- GEMM: out = X@W0 + sum_r agg_r @ W_r  (agg pre-scaled) ----------------
// 512 threads, warp tile 32x32, cp.async 3-stage ring (unchanged from R12).
#define STAGE_BYTES 65536
#define SMEM_TOTAL  (3 * STAGE_BYTES)    // 196608

__device__ __forceinline__ void cp16(uint32_t dst, const void* src, int bytes) {
    asm volatile("cp.async.cg.shared.global [%0], [%1], 16, %2;"
                 :: "r"(dst), "l"(src), "r"(bytes) : "memory");
}
#define CP_COMMIT() asm volatile("cp.async.commit_group;" ::: "memory")
#define CP_WAIT(n)  asm volatile("cp.async.wait_group %0;" :: "n"(n) : "memory")

__device__ __forceinline__ void ldmx4(uint32_t* r, uint32_t addr) {
    asm volatile("ldmatrix.sync.aligned.m8n8.x4.shared.b16 {%0,%1,%2,%3}, [%4];"
                 : "=r"(r[0]), "=r"(r[1]), "=r"(r[2]), "=r"(r[3]) : "r"(addr));
}
__device__ __forceinline__ void mma16816h(float* c, const uint32_t* a,
                                          uint32_t b0, uint32_t b1) {
    asm volatile("mma.sync.aligned.m16n8k16.row.col.f32.f16.f16.f32 "
                 "{%0,%1,%2,%3}, {%4,%5,%6,%7}, {%8,%9}, {%0,%1,%2,%3};"
                 : "+f"(c[0]), "+f"(c[1]), "+f"(c[2]), "+f"(c[3])
                 : "r"(a[0]), "r"(a[1]), "r"(a[2]), "r"(a[3]), "r"(b0), "r"(b1));
}

__global__ __launch_bounds__(512, 1)
void gemm_fused_kernel(float* __restrict__ out, int N)
{
    extern __shared__ char smem[];
    uint32_t sb = smem_u32(smem);
    const int t = threadIdx.x, ln = t & 31, wid = t >> 5;
    const int row0 = blockIdx.x * 128;

    const int kb  = (t & 15) * 16;           // byte offset in 256B row
    const int col = kb >> 1;                 // half index
    const int rbase = t >> 4;                // row 0..31

    auto issue = [&](int g, int buf) {
        const __half* A = (g < MAX_R) ? (g_agg + (size_t)g * (size_t)N * DD) : g_x16;
        const __half* B = g_wh + (size_t)g * DD * DD;
        uint32_t aBuf = sb + buf * STAGE_BYTES;
        uint32_t bBuf = aBuf + 32768;
        #pragma unroll
        for (int it = 0; it < 4; ++it) {
            int row = rbase + it * 32;
            int gr = row0 + row;
            uint32_t dst = (uint32_t)(row * 256 + (kb ^ ((row & 7) << 4)));
            int ok = (gr < N);
            const __half* ap = A + (size_t)(ok ? gr : 0) * DD + col;
            cp16(aBuf + dst, ap, ok ? 16 : 0);           // zero-fill tail rows
            cp16(bBuf + dst, B + (size_t)row * DD + col, 16);
        }
    };

    float c[2][4][4];
    #pragma unroll
    for (int mi = 0; mi < 2; ++mi)
        #pragma unroll
        for (int j = 0; j < 4; ++j)
            #pragma unroll
            for (int q = 0; q < 4; ++q) c[mi][j][q] = 0.f;

    const int m0 = (wid & 3) * 32;     // 4 M-warps
    const int n0 = (wid >> 2) * 32;    // 4 N-warps
    const int rA   = ln & 15;
    const int koff = ln & 16;

    issue(0, 0); CP_COMMIT();
    issue(1, 1); CP_COMMIT();
    issue(2, 2); CP_COMMIT();

    for (int g = 0; g < NG; ++g) {
        if (g <= NG - 3)      { CP_WAIT(2); }
        else if (g == NG - 2) { CP_WAIT(1); }
        else                  { CP_WAIT(0); }
        __syncthreads();

        int buf = g % 3;
        uint32_t aBase = sb + buf * STAGE_BYTES;
        uint32_t bBase = aBase + 32768;
        #pragma unroll
        for (int ks = 0; ks < 8; ++ks) {
            int kbb = ks * 32;
            uint32_t ah[8], b[8];
            #pragma unroll
            for (int mi = 0; mi < 2; ++mi) {
                int r = m0 + mi * 16 + rA;
                ldmx4(ah + mi * 4, aBase + r * 256 + ((kbb + koff) ^ ((r & 7) << 4)));
            }
            #pragma unroll
            for (int j2 = 0; j2 < 2; ++j2) {
                int r = n0 + j2 * 16 + rA;
                ldmx4(b + j2 * 4, bBase + r * 256 + ((kbb + koff) ^ ((r & 7) << 4)));
            }
            #pragma unroll
            for (int mi = 0; mi < 2; ++mi)
                #pragma unroll
                for (int j2 = 0; j2 < 2; ++j2) {
                    mma16816h(c[mi][2 * j2],     ah + mi * 4, b[j2 * 4 + 0], b[j2 * 4 + 2]);
                    mma16816h(c[mi][2 * j2 + 1], ah + mi * 4, b[j2 * 4 + 1], b[j2 * 4 + 3]);
                }
        }
        __syncthreads();
        if (g + 3 < NG) { issue(g + 3, buf); CP_COMMIT(); }
    }

    #pragma unroll
    for (int mi = 0; mi < 2; ++mi) {
        int r0 = row0 + m0 + mi * 16 + (ln >> 2);
        #pragma unroll
        for (int j = 0; j < 4; ++j) {
            int colo = n0 + j * 8 + (ln & 3) * 2;
            if (r0 < N)
                *(float2*)(out + (size_t)r0 * DD + colo) = make_float2(c[mi][j][0], c[mi][j][1]);
            if (r0 + 8 < N)
                *(float2*)(out + (size_t)(r0 + 8) * DD + colo) = make_float2(c[mi][j][2], c[mi][j][3]);
        }
    }
}

extern "C" void kernel_launch(void* const* d_in, const int* in_sizes, int n_in,
                              void* d_out, int out_size)
{
    const float* X        = (const float*)d_in[0];
    const float* W        = (const float*)d_in[1];
    const float* W0       = (const float*)d_in[2];
    const float* inv_norm = (const float*)d_in[3];
    const int*   esrc     = (const int*)d_in[4];
    const int*   edst     = (const int*)d_in[5];
    const int*   erel     = (const int*)d_in[6];
    float* out = (float*)d_out;

    int N = in_sizes[0] / DD;            // 50000
    int E = in_sizes[4];                 // 800000

    // Phase 0: prep (zero seg counters + cursor, fp16 X, fp16 W^T)
    int prep_items = CZ + XC + WC + 1;
    prep_kernel<<<(prep_items + 255) / 256, 256>>>(X, W, W0);

    // Phase 1: CSR build
    count_kernel<<<(E + 255) / 256, 256>>>(edst, erel, E, N);
    offsets_kernel<<<(RN + 1023) / 1024, 1024>>>();
    reorder_kernel<<<(E + 255) / 256, 256>>>(esrc, edst, erel, E, N);

    // Phase 2: gather segment-sums into agg (fp32 accum, no atomics, no zero pass)
    int segs_per_block = (256 / 32) * 2;                 // 16 segments per 256-thread block
    gather_kernel<<<(RN + segs_per_block - 1) / segs_per_block, 256>>>(inv_norm);

    // Phase 3: pipelined GEMM — out = X@W0 + sum_r agg_r @ W_r
    cudaFuncSetAttribute(gemm_fused_kernel, cudaFuncAttributeMaxDynamicSharedMemorySize, SMEM_TOTAL);
    gemm_fused_kernel<<<(N + 127) / 128, 512, SMEM_TOTAL>>>(out, N);
}